// round 1
// baseline (speedup 1.0000x reference)
#include <cuda_runtime.h>

// Problem constants (fixed by the reference: B=8, S=2048, D=1024)
#define BB 8
#define SS 2048
#define DD 1024
#define CHUNKS 32
#define ROWS_PER_CHUNK (SS / CHUNKS)   // 64

// Scratch for per-chunk column sums: written (not accumulated) every call,
// so no zero-init needed. 8*32*1024*4 = 1 MB.
__device__ float g_partial[BB * CHUNKS * DD];

// ---------------------------------------------------------------------------
// Kernel A: per-(batch, chunk) column sum of x over the S dimension.
// grid = (CHUNKS, B), block = 256 threads; thread t owns columns [4t, 4t+3].
// Each row read is 256 lanes * 16B = 4 KB fully coalesced.
// ---------------------------------------------------------------------------
__global__ __launch_bounds__(256) void colsum_kernel(const float* __restrict__ x) {
    const int c = blockIdx.x;
    const int b = blockIdx.y;
    const int t = threadIdx.x;  // 0..255

    const float4* __restrict__ xp =
        reinterpret_cast<const float4*>(x + ((size_t)b * SS + (size_t)c * ROWS_PER_CHUNK) * DD) + t;

    // 4 independent accumulators per component via 4-way row unroll to expose MLP
    float4 a0 = make_float4(0.f, 0.f, 0.f, 0.f);
    float4 a1 = make_float4(0.f, 0.f, 0.f, 0.f);
    float4 a2 = make_float4(0.f, 0.f, 0.f, 0.f);
    float4 a3 = make_float4(0.f, 0.f, 0.f, 0.f);

    #pragma unroll
    for (int s = 0; s < ROWS_PER_CHUNK; s += 4) {
        float4 v0 = xp[(size_t)(s + 0) * (DD / 4)];
        float4 v1 = xp[(size_t)(s + 1) * (DD / 4)];
        float4 v2 = xp[(size_t)(s + 2) * (DD / 4)];
        float4 v3 = xp[(size_t)(s + 3) * (DD / 4)];
        a0.x += v0.x; a0.y += v0.y; a0.z += v0.z; a0.w += v0.w;
        a1.x += v1.x; a1.y += v1.y; a1.z += v1.z; a1.w += v1.w;
        a2.x += v2.x; a2.y += v2.y; a2.z += v2.z; a2.w += v2.w;
        a3.x += v3.x; a3.y += v3.y; a3.z += v3.z; a3.w += v3.w;
    }

    float4 acc;
    acc.x = (a0.x + a1.x) + (a2.x + a3.x);
    acc.y = (a0.y + a1.y) + (a2.y + a3.y);
    acc.z = (a0.z + a1.z) + (a2.z + a3.z);
    acc.w = (a0.w + a1.w) + (a2.w + a3.w);

    reinterpret_cast<float4*>(g_partial + ((size_t)b * CHUNKS + c) * DD)[t] = acc;
}

// ---------------------------------------------------------------------------
// Kernel B: out[b, e] = dot(xsum[b, :], Wv[e, :]) + S * bv[e]
// grid = (16, B) -> 128 CTAs, 256 threads (8 warps); block handles 64 outputs.
// Stage 1: reduce the 32 chunk partials for batch b into smem xsum (4 KB).
// Stage 2: warp-per-output dot product, float4 loads, butterfly reduce.
// ---------------------------------------------------------------------------
__global__ __launch_bounds__(256) void gemv_kernel(const float* __restrict__ Wv,
                                                   const float* __restrict__ bv,
                                                   float* __restrict__ out) {
    __shared__ float xs[DD];

    const int tile = blockIdx.x;   // 0..15 : which 64 outputs
    const int b    = blockIdx.y;
    const int t    = threadIdx.x;  // 0..255

    // Stage 1: xsum[b, 4t..4t+3] = sum over 32 chunk partials (deterministic order)
    {
        const float4* __restrict__ pp =
            reinterpret_cast<const float4*>(g_partial + (size_t)b * CHUNKS * DD);
        float4 acc = make_float4(0.f, 0.f, 0.f, 0.f);
        #pragma unroll
        for (int c = 0; c < CHUNKS; ++c) {
            float4 v = pp[(size_t)c * (DD / 4) + t];
            acc.x += v.x; acc.y += v.y; acc.z += v.z; acc.w += v.w;
        }
        reinterpret_cast<float4*>(xs)[t] = acc;
    }
    __syncthreads();

    const int warp = t >> 5;
    const int lane = t & 31;
    const float4* __restrict__ xsv = reinterpret_cast<const float4*>(xs);

    #pragma unroll
    for (int j = 0; j < 8; ++j) {
        const int e = tile * 64 + warp * 8 + j;
        const float4* __restrict__ wrow = reinterpret_cast<const float4*>(Wv + (size_t)e * DD);

        float sum = 0.f;
        #pragma unroll
        for (int i = 0; i < 8; ++i) {
            float4 w  = wrow[lane + 32 * i];
            float4 xv = xsv[lane + 32 * i];
            sum += w.x * xv.x + w.y * xv.y + w.z * xv.z + w.w * xv.w;
        }
        #pragma unroll
        for (int off = 16; off; off >>= 1)
            sum += __shfl_xor_sync(0xffffffffu, sum, off);

        if (lane == 0)
            out[(size_t)b * DD + e] = sum + (float)SS * bv[e];
    }
}

// ---------------------------------------------------------------------------
// kernel_launch — graph-capturable, allocation-free, deterministic.
// Input order (metadata): 0=x, 1=Wq, 2=bq, 3=Wk, 4=bk, 5=Wv, 6=bv
// ---------------------------------------------------------------------------
extern "C" void kernel_launch(void* const* d_in, const int* in_sizes, int n_in,
                              void* d_out, int out_size) {
    (void)in_sizes; (void)n_in; (void)out_size;
    const float* x  = (const float*)d_in[0];
    const float* Wv = (const float*)d_in[5];
    const float* bv = (const float*)d_in[6];
    float* out = (float*)d_out;

    colsum_kernel<<<dim3(CHUNKS, BB), 256>>>(x);
    gemv_kernel<<<dim3(DD / 64, BB), 256>>>(Wv, bv, out);
}